// round 5
// baseline (speedup 1.0000x reference)
#include <cuda_runtime.h>
#include <math.h>

#define NB 64
#define N 1024
#define ITERS 10
#define NCHUNK 8

// Scratch (allocation-free)
__device__ __align__(16) float g_u[NB * N];
__device__ __align__(16) float g_v[NB * N];
// Col-pass partials: [batch][chunk][col]
__device__ __align__(16) float g_pm[NB * NCHUNK * N];
__device__ __align__(16) float g_ps[NB * NCHUNK * N];
// Per-batch arrival counters for the fused combine
__device__ unsigned int g_cnt[NB];

__device__ __forceinline__ float clampA(float m) {
    return fminf(fmaxf(m, -25.0f), 25.0f) * 10.0f;   // clip(M,±25)/0.1
}

__global__ void init_kernel() {
    int t = blockIdx.x * blockDim.x + threadIdx.x;
    if (t < NB * N) g_v[t] = 0.0f;
    if (t < NB) g_cnt[t] = 0u;
}

// ---------------------------------------------------------------------------
// Row pass: u[b][i] = LSE_j( A[b][i][j] - v[b][j] ). Two warps per row.
// Block 256 = 4 rows x 64 threads. Each thread holds 16 values (4 float4s).
// ---------------------------------------------------------------------------
__global__ void __launch_bounds__(256) row_lse_kernel(const float* __restrict__ M) {
    int rl   = threadIdx.x >> 6;        // 0..3 row within block
    int tr   = threadIdx.x & 63;        // thread within row
    int half = tr >> 5;
    int lane = tr & 31;
    size_t r = (size_t)blockIdx.x * 4 + rl;     // global row id
    int b = (int)(r >> 10);

    const float4* __restrict__ row4 = reinterpret_cast<const float4*>(M) + r * (N / 4);
    const float4* __restrict__ v4   = reinterpret_cast<const float4*>(g_v + b * N);

    float x[16];
    float mx = -1e30f;
#pragma unroll
    for (int k = 0; k < 4; k++) {
        int idx = tr + 64 * k;
        float4 a = row4[idx];
        float4 v = v4[idx];
        float x0 = clampA(a.x) - v.x;
        float x1 = clampA(a.y) - v.y;
        float x2 = clampA(a.z) - v.z;
        float x3 = clampA(a.w) - v.w;
        x[4 * k + 0] = x0; x[4 * k + 1] = x1;
        x[4 * k + 2] = x2; x[4 * k + 3] = x3;
        mx = fmaxf(mx, fmaxf(fmaxf(x0, x1), fmaxf(x2, x3)));
    }
#pragma unroll
    for (int o = 16; o > 0; o >>= 1)
        mx = fmaxf(mx, __shfl_xor_sync(0xFFFFFFFFu, mx, o));

    __shared__ float rm[4][2];
    __shared__ float rs[4][2];
    if (lane == 0) rm[rl][half] = mx;
    __syncthreads();
    mx = fmaxf(rm[rl][0], rm[rl][1]);

    float s = 0.0f;
#pragma unroll
    for (int k = 0; k < 16; k++)
        s += __expf(x[k] - mx);
#pragma unroll
    for (int o = 16; o > 0; o >>= 1)
        s += __shfl_xor_sync(0xFFFFFFFFu, s, o);
    if (lane == 0) rs[rl][half] = s;
    __syncthreads();

    if (tr == 0)
        g_u[r] = mx + __logf(rs[rl][0] + rs[rl][1]);
}

// ---------------------------------------------------------------------------
// Col pass: per-tile partial (m, s) for each column; the LAST block of each
// batch (atomic counter) merges the 8 row-chunk partials into v[b][:] in its
// tail, eliminating the separate combine kernel.
// Tile = 64 cols x 128 rows. Block 256 = (16 float4-cols x 16 row-groups).
// Batches processed in DESCENDING order (L2 ping-pong with the row pass).
// ---------------------------------------------------------------------------
__global__ void __launch_bounds__(256) col_lse_partial_kernel(const float* __restrict__ M) {
    int b  = NB - 1 - (int)blockIdx.z;
    int tx = threadIdx.x & 15;          // float4-col within tile
    int ty = threadIdx.x >> 4;          // 0..15 row group
    int j4 = blockIdx.x * 16 + tx;      // global float4 col (0..255)
    int i0 = blockIdx.y * 128;          // row chunk start

    __shared__ float us[128];
    __shared__ float4 smv[16][17];      // per-(ty) per-(tx) partials, padded

    if (threadIdx.x < 128)
        us[threadIdx.x] = g_u[b * N + i0 + threadIdx.x];
    __syncthreads();

    const float4* __restrict__ base = reinterpret_cast<const float4*>(M)
                                      + (size_t)b * N * (N / 4) + j4;

    float4 xv[8];
    float4 mx = make_float4(-1e30f, -1e30f, -1e30f, -1e30f);
#pragma unroll
    for (int k = 0; k < 8; k++) {
        int i = ty + 16 * k;
        float4 a = base[(size_t)(i0 + i) * (N / 4)];
        float u = us[i];
        float4 t;
        t.x = clampA(a.x) - u;
        t.y = clampA(a.y) - u;
        t.z = clampA(a.z) - u;
        t.w = clampA(a.w) - u;
        xv[k] = t;
        mx.x = fmaxf(mx.x, t.x); mx.y = fmaxf(mx.y, t.y);
        mx.z = fmaxf(mx.z, t.z); mx.w = fmaxf(mx.w, t.w);
    }

    smv[ty][tx] = mx;
    __syncthreads();

    // Column max across the 16 row-groups (each thread for its 4 columns)
    float4 MX = smv[0][tx];
#pragma unroll
    for (int k = 1; k < 16; k++) {
        float4 t = smv[k][tx];
        MX.x = fmaxf(MX.x, t.x); MX.y = fmaxf(MX.y, t.y);
        MX.z = fmaxf(MX.z, t.z); MX.w = fmaxf(MX.w, t.w);
    }

    float4 s = make_float4(0.f, 0.f, 0.f, 0.f);
#pragma unroll
    for (int k = 0; k < 8; k++) {
        s.x += __expf(xv[k].x - MX.x);
        s.y += __expf(xv[k].y - MX.y);
        s.z += __expf(xv[k].z - MX.z);
        s.w += __expf(xv[k].w - MX.w);
    }
    __syncthreads();
    smv[ty][tx] = s;
    __syncthreads();

    if (ty == 0) {
        float4 SS = smv[0][tx];
#pragma unroll
        for (int k = 1; k < 16; k++) {
            float4 t = smv[k][tx];
            SS.x += t.x; SS.y += t.y; SS.z += t.z; SS.w += t.w;
        }
        size_t p = ((size_t)b * NCHUNK + blockIdx.y) * (N / 4) + j4;
        reinterpret_cast<float4*>(g_pm)[p] = MX;
        reinterpret_cast<float4*>(g_ps)[p] = SS;
    }

    // ---- fused combine: last arriving block of this batch merges partials ----
    __threadfence();
    __shared__ bool amLast;
    if (threadIdx.x == 0) {
        unsigned int prev = atomicAdd(&g_cnt[b], 1u);
        amLast = (prev == (unsigned int)((N / 64) * NCHUNK - 1));
    }
    __syncthreads();

    if (amLast) {
        int q4 = threadIdx.x;           // one float4 column per thread (0..255)
        size_t pb = (size_t)b * NCHUNK * (N / 4) + q4;
        float4 m = reinterpret_cast<const float4*>(g_pm)[pb];
        float4 sv = reinterpret_cast<const float4*>(g_ps)[pb];
#pragma unroll
        for (int c = 1; c < NCHUNK; c++) {
            size_t p = pb + (size_t)c * (N / 4);
            float4 pm = reinterpret_cast<const float4*>(g_pm)[p];
            float4 ps = reinterpret_cast<const float4*>(g_ps)[p];
            float nm;
            nm = fmaxf(m.x, pm.x); sv.x = sv.x * __expf(m.x - nm) + ps.x * __expf(pm.x - nm); m.x = nm;
            nm = fmaxf(m.y, pm.y); sv.y = sv.y * __expf(m.y - nm) + ps.y * __expf(pm.y - nm); m.y = nm;
            nm = fmaxf(m.z, pm.z); sv.z = sv.z * __expf(m.z - nm) + ps.z * __expf(pm.z - nm); m.z = nm;
            nm = fmaxf(m.w, pm.w); sv.w = sv.w * __expf(m.w - nm) + ps.w * __expf(pm.w - nm); m.w = nm;
        }
        float4 v;
        v.x = m.x + __logf(sv.x);
        v.y = m.y + __logf(sv.y);
        v.z = m.z + __logf(sv.z);
        v.w = m.w + __logf(sv.w);
        reinterpret_cast<float4*>(g_v)[b * (N / 4) + q4] = v;
        if (threadIdx.x == 0) g_cnt[b] = 0u;    // reset for next launch
    }
}

// ---------------------------------------------------------------------------
// Last col pass fused with output: compute v_j in-block (full column), then
// write exp(x - v_j) from register-resident values. Descending batch order.
// ---------------------------------------------------------------------------
__global__ void __launch_bounds__(1024) col_lse_finalize_kernel(const float* __restrict__ M,
                                                                float* __restrict__ out) {
    int b = NB - 1 - (int)blockIdx.y;
    int cx = threadIdx.x;
    int y  = threadIdx.y;
    int j = blockIdx.x * 32 + cx;

    __shared__ float us[N];
    __shared__ float sm_m[32][33];
    __shared__ float sm_s[32][33];

    us[y * 32 + cx] = g_u[b * N + y * 32 + cx];
    __syncthreads();

    const float* __restrict__ base = M + (size_t)b * N * N + j;

    float xv[32];
    float mx = -1e30f;
#pragma unroll
    for (int k = 0; k < 32; k++) {
        int i = y + 32 * k;
        float a = base[(size_t)i * N];
        float t = clampA(a) - us[i];
        xv[k] = t;
        mx = fmaxf(mx, t);
    }

    sm_m[y][cx] = mx;
    __syncthreads();

    float MX = sm_m[0][cx];
#pragma unroll
    for (int k = 1; k < 32; k++)
        MX = fmaxf(MX, sm_m[k][cx]);

    float s = 0.0f;
#pragma unroll
    for (int k = 0; k < 32; k++)
        s += __expf(xv[k] - MX);

    sm_s[y][cx] = s;
    __syncthreads();

    float SS = sm_s[0][cx];
#pragma unroll
    for (int k = 1; k < 32; k++)
        SS += sm_s[k][cx];
    float V = MX + __logf(SS);

    float* __restrict__ obase = out + (size_t)b * N * N + j;
#pragma unroll
    for (int k = 0; k < 32; k++) {
        int i = y + 32 * k;
        obase[(size_t)i * N] = __expf(xv[k] - V);
    }
}

extern "C" void kernel_launch(void* const* d_in, const int* in_sizes, int n_in,
                              void* d_out, int out_size) {
    const float* M = (const float*)d_in[0];
    float* out = (float*)d_out;

    init_kernel<<<(NB * N + 255) / 256, 256>>>();

    for (int it = 0; it < ITERS; it++) {
        row_lse_kernel<<<(NB * N) / 4, 256>>>(M);
        if (it < ITERS - 1) {
            col_lse_partial_kernel<<<dim3(N / 64, NCHUNK, NB), 256>>>(M);
        } else {
            col_lse_finalize_kernel<<<dim3(N / 32, NB), dim3(32, 32)>>>(M, out);
        }
    }
}